// round 14
// baseline (speedup 1.0000x reference)
#include <cuda_runtime.h>
#include <cuda_fp16.h>
#include <cstdint>

// Fused LSTM cell, sm_103 family-generic (no tcgen05 in this toolchain).
// Pass 1 (single kernel): fp32 -> fp16(rn):
//   AscrH = [x|h] (32768 x 1024 row-major)
//   BscrH = [Wx;Wh]^T gate-permuted [N'=2048][K=1024]:
//     n' = nt*128 + wn*64 + g*16 + jj  <->  weight col g*512 + nt*32 + wn*16 + jj
// Pass 2: 128x128x1024 GEMM per CTA, 256 threads (8 warps, warp tile 32x64),
//   cp.async 3-stage mbarrier pipeline (no __syncthreads in main loop),
//   issue(kt+2) HOISTED ABOVE compute(kt) so stage loads overlap the whole
//   MMA chain, A/B fragment double buffering, early empty-arrive,
//   L2-prefetched Cin, mma.sync.m16n8k16, register LSTM epilogue. 2 CTAs/SM.

#define BATCH 32768
#define DH 512
#define KTOT 1024
#define NTOT 2048

#define BM 128
#define BN 128
#define BK 64
#define KTILES (KTOT / BK)  // 16
#define STAGES 3
#define THREADS 256

#define ROWP 72                       // halves per smem row (64 + 8 pad)
#define TILE_H (128 * ROWP)           // 9216 halves per A/B tile
#define STG_BYTES (2 * TILE_H * 2)    // 36864 B
#define STAGE_OFF 1024
#define SMEM_BYTES (STAGE_OFF + STAGES * STG_BYTES)  // 111616

#define PREP_A_BLOCKS 32768           // 8,388,608 float4 / 256
#define PREP_B_BLOCKS 2048            // 524,288 items / 256

// ---------------- device scratch ----------------
__device__ __half AscrH[(size_t)BATCH * KTOT];  // 64 MB
__device__ __half BscrH[(size_t)NTOT * KTOT];   // 4 MB

__device__ __forceinline__ uint32_t smem_u32(const void* p) {
    uint32_t a;
    asm("{ .reg .u64 t; cvta.to.shared.u64 t, %1; cvt.u32.u64 %0, t; }"
        : "=r"(a) : "l"(p));
    return a;
}
__device__ __forceinline__ void cp16(uint32_t sm, const void* g) {
    asm volatile("cp.async.cg.shared.global [%0], [%1], 16;"
                 :: "r"(sm), "l"(g) : "memory");
}
__device__ __forceinline__ void l2_prefetch(const void* g) {
    asm volatile("prefetch.global.L2 [%0];" :: "l"(g));
}
#define MBARRIER_INIT(addr, cnt) \
    asm volatile("mbarrier.init.shared.b64 [%0], %1;" :: "r"(addr), "r"(cnt) : "memory")
#define MBARRIER_ARRIVE(addr) \
    asm volatile("mbarrier.arrive.shared.b64 _, [%0];" :: "r"(addr) : "memory")
#define CP_ASYNC_MBAR_ARRIVE(addr) \
    asm volatile("cp.async.mbarrier.arrive.noinc.shared.b64 [%0];" \
                 :: "r"(addr) : "memory")
#define MBARRIER_WAIT_PARITY(addr, par) do {                                   \
    uint32_t _m = (addr), _p = (par), _d;                                      \
    asm volatile("{\n\t.reg .pred p;\n\t"                                      \
        "mbarrier.try_wait.parity.acquire.cta.shared::cta.b64 p, [%1], %2;\n\t"\
        "selp.b32 %0, 1, 0, p;\n\t}"                                           \
        : "=r"(_d) : "r"(_m), "r"(_p) : "memory");                             \
    if (!_d) {                                                                 \
        asm volatile("{\n\t.reg .pred P1;\n\t"                                 \
            "WL_%=:\n\t"                                                       \
            "mbarrier.try_wait.parity.acquire.cta.shared::cta.b64 P1, [%0], %1, 0x989680;\n\t" \
            "@P1 bra.uni WD_%=;\n\t"                                           \
            "bra.uni WL_%=;\n\t"                                               \
            "WD_%=:\n\t}" :: "r"(_m), "r"(_p) : "memory");                     \
    }                                                                          \
} while (0)

__device__ __forceinline__ void ldsm_x4(uint32_t& r0, uint32_t& r1,
                                        uint32_t& r2, uint32_t& r3,
                                        uint32_t addr) {
    asm volatile("ldmatrix.sync.aligned.m8n8.x4.shared.b16 {%0,%1,%2,%3}, [%4];"
                 : "=r"(r0), "=r"(r1), "=r"(r2), "=r"(r3) : "r"(addr));
}
__device__ __forceinline__ void mma_f16(float d[4], const uint32_t a[4],
                                        const uint32_t b0, const uint32_t b1,
                                        const float c[4]) {
    asm volatile(
        "mma.sync.aligned.m16n8k16.row.col.f32.f16.f16.f32 "
        "{%0,%1,%2,%3}, {%4,%5,%6,%7}, {%8,%9}, {%10,%11,%12,%13};\n"
        : "=f"(d[0]), "=f"(d[1]), "=f"(d[2]), "=f"(d[3])
        : "r"(a[0]), "r"(a[1]), "r"(a[2]), "r"(a[3]),
          "r"(b0), "r"(b1),
          "f"(c[0]), "f"(c[1]), "f"(c[2]), "f"(c[3]));
}

__device__ __forceinline__ float sigm(float v) { return 1.0f / (1.0f + __expf(-v)); }
__device__ __forceinline__ float tanh_fast(float v) {
    return 2.0f / (1.0f + __expf(-2.0f * v)) - 1.0f;
}

// ---------------- pass 1: merged conversion ----------------
__global__ void __launch_bounds__(256) prep_all(const float* __restrict__ x,
                                                const float* __restrict__ h,
                                                const float* __restrict__ Wx,
                                                const float* __restrict__ Wh) {
    if (blockIdx.x < PREP_A_BLOCKS) {
        size_t i = (size_t)blockIdx.x * 256 + threadIdx.x;  // float4 index
        size_t e = i * 4;
        int b = (int)(e >> 10);
        int k = (int)(e & 1023);
        const float* src = (k < 512) ? (x + (size_t)b * 512 + k)
                                     : (h + (size_t)b * 512 + (k - 512));
        float4 v = *(const float4*)src;
        __half2 h0 = __floats2half2_rn(v.x, v.y);
        __half2 h1 = __floats2half2_rn(v.z, v.w);
        uint2 o = make_uint2(*(uint32_t*)&h0, *(uint32_t*)&h1);
        *(uint2*)(AscrH + e) = o;
    } else {
        // BscrH[n'][k] = W[k][col]
        // n' = nt*128 + wn*64 + g*16 + jj, col = g*512 + nt*32 + wn*16 + jj
        size_t t = (size_t)(blockIdx.x - PREP_A_BLOCKS) * 256 + threadIdx.x;
        int np = (int)(t >> 8);          // n' 0..2047
        int kb = (int)(t & 255) * 4;     // k base
        int nt = np >> 7;
        int r = np & 127;
        int wn = r >> 6;
        int g = (r >> 4) & 3;
        int jj = r & 15;
        int col = g * 512 + nt * 32 + wn * 16 + jj;
        const float* src = (kb < 512) ? (Wx + (size_t)kb * NTOT + col)
                                      : (Wh + (size_t)(kb - 512) * NTOT + col);
        float v0 = src[0];
        float v1 = src[NTOT];
        float v2 = src[2 * NTOT];
        float v3 = src[3 * NTOT];
        __half2 h0 = __floats2half2_rn(v0, v1);
        __half2 h1 = __floats2half2_rn(v2, v3);
        uint2 o = make_uint2(*(uint32_t*)&h0, *(uint32_t*)&h1);
        *(uint2*)(BscrH + (size_t)np * KTOT + kb) = o;
    }
}

// ---------------- pass 2 ----------------
__global__ void __launch_bounds__(THREADS, 2)
lstm_gemm(const float* __restrict__ Cin, const float* __restrict__ bx,
          const float* __restrict__ bh, float* __restrict__ out) {
    extern __shared__ float smem[];
    const uint32_t sbase = smem_u32(smem);

    const int tid = threadIdx.x;
    const int warp = tid >> 5;
    const int lane = tid & 31;
    const int wm = warp & 3;   // 4 warps along M (32 rows each)
    const int wn = warp >> 2;  // 2 warps along N (64 cols each)
    const int gid = lane >> 2;
    const int tig = lane & 3;

    const int mBase = blockIdx.y * BM;
    const int nt = blockIdx.x;
    const int hjBase = nt * 32 + wn * 16;

    // mbarriers: full[s] = sbase + s*16, empty[s] = sbase + s*16 + 8
    if (tid == 0) {
#pragma unroll
        for (int s = 0; s < STAGES; ++s) {
            MBARRIER_INIT(sbase + s * 16, THREADS);  // full: cp.async arrivals
            MBARRIER_INIT(sbase + s * 16 + 8, 8);    // empty: 1 per warp
        }
    }
    __syncthreads();

    // L2-prefetch this CTA's Cin lines (read once, in the epilogue).
#pragma unroll
    for (int mt = 0; mt < 2; ++mt)
#pragma unroll
        for (int rh = 0; rh < 2; ++rh)
#pragma unroll
            for (int jh = 0; jh < 2; ++jh) {
                const int row = mBase + wm * 32 + mt * 16 + gid + rh * 8;
                l2_prefetch(Cin + (size_t)row * DH + hjBase + jh * 8 + tig * 2);
            }

    float acc[2][8][4];
#pragma unroll
    for (int mt = 0; mt < 2; ++mt)
#pragma unroll
        for (int n = 0; n < 8; ++n)
#pragma unroll
            for (int c = 0; c < 4; ++c) acc[mt][n][c] = 0.0f;

    // cp.async coordinates: 16B chunk = tid + i*256; row = chunk>>3, c = chunk&7
    const int ldR = tid >> 3;   // 0..31, +32 per i
    const int ldC = tid & 7;

    const __half* gA0 = AscrH + (size_t)(mBase + ldR) * KTOT + ldC * 8;
    const __half* gB0 = BscrH + (size_t)(nt * BN + ldR) * KTOT + ldC * 8;
    const uint32_t soff = (uint32_t)(ldR * ROWP + ldC * 8) * 2;

    // ldmatrix lane offset (bytes): rows (lane&15), k-half (lane>>4)*8 halves
    const uint32_t lmOff = (uint32_t)((lane & 15) * ROWP + (lane >> 4) * 8) * 2;
    const uint32_t aWarp = (uint32_t)(wm * 32 * ROWP) * 2 + lmOff;
    const uint32_t bWarp = (uint32_t)(wn * 64 * ROWP) * 2 + lmOff;

    auto issue = [&](int kt) {                         // kt compile-time
        const int s = kt % STAGES;
        MBARRIER_WAIT_PARITY(sbase + s * 16 + 8, ((kt / 3) & 1) ^ 1);
        const uint32_t sa = sbase + STAGE_OFF + (uint32_t)s * STG_BYTES;
        const uint32_t sb = sa + TILE_H * 2;
        const size_t kg = (size_t)kt * BK;
#pragma unroll
        for (int i = 0; i < 4; ++i) {
            cp16(sa + soff + i * 32 * ROWP * 2, gA0 + kg + (size_t)i * 32 * KTOT);
            cp16(sb + soff + i * 32 * ROWP * 2, gB0 + kg + (size_t)i * 32 * KTOT);
        }
        CP_ASYNC_MBAR_ARRIVE(sbase + s * 16);
    };

    auto compute = [&](int kt) {                       // kt compile-time
        const int s = kt % STAGES;
        MBARRIER_WAIT_PARITY(sbase + s * 16, (kt / 3) & 1);
        const uint32_t sa = sbase + STAGE_OFF + (uint32_t)s * STG_BYTES + aWarp;
        const uint32_t sb = sbase + STAGE_OFF + (uint32_t)s * STG_BYTES + TILE_H * 2 + bWarp;
        uint32_t abuf[2][2][4];
        uint32_t bbuf[2][4];
#pragma unroll
        for (int mt = 0; mt < 2; ++mt)
            ldsm_x4(abuf[0][mt][0], abuf[0][mt][1], abuf[0][mt][2], abuf[0][mt][3],
                    sa + (uint32_t)(mt * 16 * ROWP) * 2);
        ldsm_x4(bbuf[0][0], bbuf[0][1], bbuf[0][2], bbuf[0][3], sb);
#pragma unroll
        for (int ks = 0; ks < 4; ++ks) {
            const uint32_t kOff = ks * 32;  // 16 halves
            const int cur = ks & 1;
            if (ks < 3) {
#pragma unroll
                for (int mt = 0; mt < 2; ++mt)
                    ldsm_x4(abuf[cur ^ 1][mt][0], abuf[cur ^ 1][mt][1],
                            abuf[cur ^ 1][mt][2], abuf[cur ^ 1][mt][3],
                            sa + (uint32_t)(mt * 16 * ROWP) * 2 + kOff + 32);
            }
#pragma unroll
            for (int p = 0; p < 4; ++p) {
                const int bc = p & 1;
                if (p < 3) {
                    ldsm_x4(bbuf[bc ^ 1][0], bbuf[bc ^ 1][1],
                            bbuf[bc ^ 1][2], bbuf[bc ^ 1][3],
                            sb + (uint32_t)((p + 1) * 16 * ROWP) * 2 + kOff);
                } else if (ks < 3) {
                    ldsm_x4(bbuf[bc ^ 1][0], bbuf[bc ^ 1][1],
                            bbuf[bc ^ 1][2], bbuf[bc ^ 1][3],
                            sb + kOff + 32);
                }
                // early empty-arrive: at (ks==3, p==3) all LDSMs of this
                // stage have issued; the first MMA below scoreboard-waits on
                // the last fragments, so an arrive placed AFTER it is ordered
                // after every smem read of the stage has retired.
                mma_f16(acc[0][2 * p], abuf[cur][0], bbuf[bc][0],
                        bbuf[bc][2], acc[0][2 * p]);
                if (ks == 3 && p == 3) {
                    if (lane == 0) MBARRIER_ARRIVE(sbase + s * 16 + 8);
                }
                mma_f16(acc[0][2 * p + 1], abuf[cur][0], bbuf[bc][1],
                        bbuf[bc][3], acc[0][2 * p + 1]);
                mma_f16(acc[1][2 * p],     abuf[cur][1], bbuf[bc][0],
                        bbuf[bc][2], acc[1][2 * p]);
                mma_f16(acc[1][2 * p + 1], abuf[cur][1], bbuf[bc][1],
                        bbuf[bc][3], acc[1][2 * p + 1]);
            }
        }
    };

    issue(0);
    issue(1);

#pragma unroll
    for (int kt = 0; kt < KTILES; ++kt) {
        // Hoist the producer: stage (kt+2)%3 was freed by compute(kt-1), so
        // this wait passes immediately and the cp.asyncs overlap compute(kt).
        if (kt + 2 < KTILES) issue(kt + 2);
        compute(kt);
    }

    // ---------------- register epilogue ----------------
    // acc[mt][n][c]: gate = n>>1, jhalf = n&1;
    //   row = mBase + wm*32 + mt*16 + gid + (c>=2)*8
    //   jj  = jhalf*8 + tig*2 + (c&1);  hidden j = nt*32 + wn*16 + jj
    float biasI[4], biasF[4], biasO[4], biasG[4];
#pragma unroll
    for (int jh = 0; jh < 2; ++jh)
#pragma unroll
        for (int c1 = 0; c1 < 2; ++c1) {
            const int hj = hjBase + jh * 8 + tig * 2 + c1;
            biasI[jh * 2 + c1] = __ldg(bx + hj)        + __ldg(bh + hj);
            biasF[jh * 2 + c1] = __ldg(bx + 512 + hj)  + __ldg(bh + 512 + hj);
            biasO[jh * 2 + c1] = __ldg(bx + 1024 + hj) + __ldg(bh + 1024 + hj);
            biasG[jh * 2 + c1] = __ldg(bx + 1536 + hj) + __ldg(bh + 1536 + hj);
        }

    float* outH = out + (size_t)BATCH * DH;
#pragma unroll
    for (int mt = 0; mt < 2; ++mt)
#pragma unroll
        for (int rh = 0; rh < 2; ++rh)
#pragma unroll
            for (int jh = 0; jh < 2; ++jh) {
                const int row = mBase + wm * 32 + mt * 16 + gid + rh * 8;
                const int jj0 = jh * 8 + tig * 2;
                const size_t goff = (size_t)row * DH + hjBase + jj0;
                const float2 cin = *(const float2*)(Cin + goff);
                float2 cnew, hnew;
#pragma unroll
                for (int c1 = 0; c1 < 2; ++c1) {
                    const int c = rh * 2 + c1;
                    const int bidx = jh * 2 + c1;
                    const float zi = acc[mt][jh][c]     + biasI[bidx];
                    const float zf = acc[mt][2 + jh][c] + biasF[bidx];
                    const float zo = acc[mt][4 + jh][c] + biasO[bidx];
                    const float zg = acc[mt][6 + jh][c] + biasG[bidx];
                    const float ig = sigm(zi);
                    const float fg = sigm(zf);
                    const float og = sigm(zo);
                    const float gg = tanh_fast(zg);
                    const float cv = fg * ((c1 == 0) ? cin.x : cin.y) + ig * gg;
                    const float hv = og * tanh_fast(cv);
                    if (c1 == 0) { cnew.x = cv; hnew.x = hv; }
                    else         { cnew.y = cv; hnew.y = hv; }
                }
                *(float2*)(out + goff) = cnew;
                *(float2*)(outH + goff) = hnew;
            }
}

extern "C" void kernel_launch(void* const* d_in, const int* in_sizes, int n_in,
                              void* d_out, int out_size) {
    const float* x = (const float*)d_in[0];
    const float* C = (const float*)d_in[1];
    const float* h = (const float*)d_in[2];
    const float* Wx = (const float*)d_in[3];
    const float* bx = (const float*)d_in[4];
    const float* Wh = (const float*)d_in[5];
    const float* bh = (const float*)d_in[6];
    float* out = (float*)d_out;

    cudaFuncSetAttribute(lstm_gemm, cudaFuncAttributeMaxDynamicSharedMemorySize,
                         SMEM_BYTES);

    prep_all<<<PREP_A_BLOCKS + PREP_B_BLOCKS, 256>>>(x, h, Wx, Wh);
    dim3 grid(NTOT / BN, BATCH / BM);  // (16, 256)
    lstm_gemm<<<grid, THREADS, SMEM_BYTES>>>(C, bx, bh, out);
}

// round 16
// speedup vs baseline: 1.1827x; 1.1827x over previous
#include <cuda_runtime.h>
#include <cuda_fp16.h>
#include <cstdint>

// Fused LSTM cell, sm_103 family-generic (no tcgen05 in this toolchain).
// Pass 1 (single kernel): fp32 -> fp16(rn):
//   AscrH = [x|h] (32768 x 1024 row-major)  -- 8 halves/thread, uint4 stores
//   BscrH = [Wx;Wh]^T gate-permuted [N'=2048][K=1024]:
//     n' = nt*128 + wn*64 + g*16 + jj  <->  weight col g*512 + nt*32 + wn*16 + jj
// Pass 2 (= best R10 config): 128x128x1024 GEMM per CTA, 256 threads
//   (8 warps, warp tile 32x64), cp.async 3-stage mbarrier pipeline (no
//   __syncthreads in main loop), A/B fragment double buffering,
//   mma.sync.m16n8k16, register LSTM epilogue. 2 CTAs/SM (16 warps/SM).

#define BATCH 32768
#define DH 512
#define KTOT 1024
#define NTOT 2048

#define BM 128
#define BN 128
#define BK 64
#define KTILES (KTOT / BK)  // 16
#define STAGES 3
#define THREADS 256

#define ROWP 72                       // halves per smem row (64 + 8 pad)
#define TILE_H (128 * ROWP)           // 9216 halves per A/B tile
#define STG_BYTES (2 * TILE_H * 2)    // 36864 B
#define STAGE_OFF 1024
#define SMEM_BYTES (STAGE_OFF + STAGES * STG_BYTES)  // 111616

#define PREP_A_BLOCKS 16384           // 4,194,304 uint4-writers / 256
#define PREP_B_BLOCKS 2048            // 524,288 items / 256

// ---------------- device scratch ----------------
__device__ __half AscrH[(size_t)BATCH * KTOT];  // 64 MB
__device__ __half BscrH[(size_t)NTOT * KTOT];   // 4 MB

__device__ __forceinline__ uint32_t smem_u32(const void* p) {
    uint32_t a;
    asm("{ .reg .u64 t; cvta.to.shared.u64 t, %1; cvt.u32.u64 %0, t; }"
        : "=r"(a) : "l"(p));
    return a;
}
__device__ __forceinline__ void cp16(uint32_t sm, const void* g) {
    asm volatile("cp.async.cg.shared.global [%0], [%1], 16;"
                 :: "r"(sm), "l"(g) : "memory");
}
#define MBARRIER_INIT(addr, cnt) \
    asm volatile("mbarrier.init.shared.b64 [%0], %1;" :: "r"(addr), "r"(cnt) : "memory")
#define MBARRIER_ARRIVE(addr) \
    asm volatile("mbarrier.arrive.shared.b64 _, [%0];" :: "r"(addr) : "memory")
#define CP_ASYNC_MBAR_ARRIVE(addr) \
    asm volatile("cp.async.mbarrier.arrive.noinc.shared.b64 [%0];" \
                 :: "r"(addr) : "memory")
#define MBARRIER_WAIT_PARITY(addr, par) do {                                   \
    uint32_t _m = (addr), _p = (par), _d;                                      \
    asm volatile("{\n\t.reg .pred p;\n\t"                                      \
        "mbarrier.try_wait.parity.acquire.cta.shared::cta.b64 p, [%1], %2;\n\t"\
        "selp.b32 %0, 1, 0, p;\n\t}"                                           \
        : "=r"(_d) : "r"(_m), "r"(_p) : "memory");                             \
    if (!_d) {                                                                 \
        asm volatile("{\n\t.reg .pred P1;\n\t"                                 \
            "WL_%=:\n\t"                                                       \
            "mbarrier.try_wait.parity.acquire.cta.shared::cta.b64 P1, [%0], %1, 0x989680;\n\t" \
            "@P1 bra.uni WD_%=;\n\t"                                           \
            "bra.uni WL_%=;\n\t"                                               \
            "WD_%=:\n\t}" :: "r"(_m), "r"(_p) : "memory");                     \
    }                                                                          \
} while (0)

__device__ __forceinline__ void ldsm_x4(uint32_t& r0, uint32_t& r1,
                                        uint32_t& r2, uint32_t& r3,
                                        uint32_t addr) {
    asm volatile("ldmatrix.sync.aligned.m8n8.x4.shared.b16 {%0,%1,%2,%3}, [%4];"
                 : "=r"(r0), "=r"(r1), "=r"(r2), "=r"(r3) : "r"(addr));
}
__device__ __forceinline__ void mma_f16(float d[4], const uint32_t a[4],
                                        const uint32_t b0, const uint32_t b1,
                                        const float c[4]) {
    asm volatile(
        "mma.sync.aligned.m16n8k16.row.col.f32.f16.f16.f32 "
        "{%0,%1,%2,%3}, {%4,%5,%6,%7}, {%8,%9}, {%10,%11,%12,%13};\n"
        : "=f"(d[0]), "=f"(d[1]), "=f"(d[2]), "=f"(d[3])
        : "r"(a[0]), "r"(a[1]), "r"(a[2]), "r"(a[3]),
          "r"(b0), "r"(b1),
          "f"(c[0]), "f"(c[1]), "f"(c[2]), "f"(c[3]));
}

__device__ __forceinline__ float sigm(float v) { return 1.0f / (1.0f + __expf(-v)); }
__device__ __forceinline__ float tanh_fast(float v) {
    return 2.0f / (1.0f + __expf(-2.0f * v)) - 1.0f;
}

// ---------------- pass 1: merged conversion ----------------
__global__ void __launch_bounds__(256) prep_all(const float* __restrict__ x,
                                                const float* __restrict__ h,
                                                const float* __restrict__ Wx,
                                                const float* __restrict__ Wh) {
    if (blockIdx.x < PREP_A_BLOCKS) {
        // 8 halves per thread: two float4 reads -> one uint4 (16 B) store.
        size_t i = (size_t)blockIdx.x * 256 + threadIdx.x;
        size_t e = i * 8;
        int b = (int)(e >> 10);
        int k = (int)(e & 1023);     // multiple of 8; stays within x or h half
        const float* src = (k < 512) ? (x + (size_t)b * 512 + k)
                                     : (h + (size_t)b * 512 + (k - 512));
        float4 v0 = *(const float4*)src;
        float4 v1 = *(const float4*)(src + 4);
        __half2 h0 = __floats2half2_rn(v0.x, v0.y);
        __half2 h1 = __floats2half2_rn(v0.z, v0.w);
        __half2 h2 = __floats2half2_rn(v1.x, v1.y);
        __half2 h3 = __floats2half2_rn(v1.z, v1.w);
        uint4 o = make_uint4(*(uint32_t*)&h0, *(uint32_t*)&h1,
                             *(uint32_t*)&h2, *(uint32_t*)&h3);
        *(uint4*)(AscrH + e) = o;
    } else {
        // BscrH[n'][k] = W[k][col]
        // n' = nt*128 + wn*64 + g*16 + jj, col = g*512 + nt*32 + wn*16 + jj
        size_t t = (size_t)(blockIdx.x - PREP_A_BLOCKS) * 256 + threadIdx.x;
        int np = (int)(t >> 8);          // n' 0..2047
        int kb = (int)(t & 255) * 4;     // k base
        int nt = np >> 7;
        int r = np & 127;
        int wn = r >> 6;
        int g = (r >> 4) & 3;
        int jj = r & 15;
        int col = g * 512 + nt * 32 + wn * 16 + jj;
        const float* src = (kb < 512) ? (Wx + (size_t)kb * NTOT + col)
                                      : (Wh + (size_t)(kb - 512) * NTOT + col);
        float v0 = src[0];
        float v1 = src[NTOT];
        float v2 = src[2 * NTOT];
        float v3 = src[3 * NTOT];
        __half2 h0 = __floats2half2_rn(v0, v1);
        __half2 h1 = __floats2half2_rn(v2, v3);
        uint2 o = make_uint2(*(uint32_t*)&h0, *(uint32_t*)&h1);
        *(uint2*)(BscrH + (size_t)np * KTOT + kb) = o;
    }
}

// ---------------- pass 2 (exact R10 best configuration) ----------------
__global__ void __launch_bounds__(THREADS, 2)
lstm_gemm(const float* __restrict__ Cin, const float* __restrict__ bx,
          const float* __restrict__ bh, float* __restrict__ out) {
    extern __shared__ float smem[];
    const uint32_t sbase = smem_u32(smem);

    const int tid = threadIdx.x;
    const int warp = tid >> 5;
    const int lane = tid & 31;
    const int wm = warp & 3;   // 4 warps along M (32 rows each)
    const int wn = warp >> 2;  // 2 warps along N (64 cols each)
    const int gid = lane >> 2;
    const int tig = lane & 3;

    const int mBase = blockIdx.y * BM;
    const int nt = blockIdx.x;

    // mbarriers: full[s] = sbase + s*16, empty[s] = sbase + s*16 + 8
    if (tid == 0) {
#pragma unroll
        for (int s = 0; s < STAGES; ++s) {
            MBARRIER_INIT(sbase + s * 16, THREADS);  // full: cp.async arrivals
            MBARRIER_INIT(sbase + s * 16 + 8, 8);    // empty: 1 per warp
        }
    }
    __syncthreads();

    float acc[2][8][4];
#pragma unroll
    for (int mt = 0; mt < 2; ++mt)
#pragma unroll
        for (int n = 0; n < 8; ++n)
#pragma unroll
            for (int c = 0; c < 4; ++c) acc[mt][n][c] = 0.0f;

    // cp.async coordinates: 16B chunk = tid + i*256; row = chunk>>3, c = chunk&7
    const int ldR = tid >> 3;   // 0..31, +32 per i
    const int ldC = tid & 7;

    const __half* gA0 = AscrH + (size_t)(mBase + ldR) * KTOT + ldC * 8;
    const __half* gB0 = BscrH + (size_t)(nt * BN + ldR) * KTOT + ldC * 8;
    const uint32_t soff = (uint32_t)(ldR * ROWP + ldC * 8) * 2;

    // ldmatrix lane offset (bytes): rows (lane&15), k-half (lane>>4)*8 halves
    const uint32_t lmOff = (uint32_t)((lane & 15) * ROWP + (lane >> 4) * 8) * 2;
    const uint32_t aWarp = (uint32_t)(wm * 32 * ROWP) * 2 + lmOff;
    const uint32_t bWarp = (uint32_t)(wn * 64 * ROWP) * 2 + lmOff;

    auto issue = [&](int kt) {                         // kt compile-time
        const int s = kt % STAGES;
        MBARRIER_WAIT_PARITY(sbase + s * 16 + 8, ((kt / 3) & 1) ^ 1);
        const uint32_t sa = sbase + STAGE_OFF + (uint32_t)s * STG_BYTES;
        const uint32_t sb = sa + TILE_H * 2;
        const size_t kg = (size_t)kt * BK;
#pragma unroll
        for (int i = 0; i < 4; ++i) {
            cp16(sa + soff + i * 32 * ROWP * 2, gA0 + kg + (size_t)i * 32 * KTOT);
            cp16(sb + soff + i * 32 * ROWP * 2, gB0 + kg + (size_t)i * 32 * KTOT);
        }
        CP_ASYNC_MBAR_ARRIVE(sbase + s * 16);
    };

    auto compute = [&](int kt) {                       // kt compile-time
        const int s = kt % STAGES;
        MBARRIER_WAIT_PARITY(sbase + s * 16, (kt / 3) & 1);
        const uint32_t sa = sbase + STAGE_OFF + (uint32_t)s * STG_BYTES + aWarp;
        const uint32_t sb = sbase + STAGE_OFF + (uint32_t)s * STG_BYTES + TILE_H * 2 + bWarp;
        uint32_t abuf[2][2][4];
        uint32_t bbuf[2][4];
#pragma unroll
        for (int mt = 0; mt < 2; ++mt)
            ldsm_x4(abuf[0][mt][0], abuf[0][mt][1], abuf[0][mt][2], abuf[0][mt][3],
                    sa + (uint32_t)(mt * 16 * ROWP) * 2);
        ldsm_x4(bbuf[0][0], bbuf[0][1], bbuf[0][2], bbuf[0][3], sb);
#pragma unroll
        for (int ks = 0; ks < 4; ++ks) {
            const uint32_t kOff = ks * 32;  // 16 halves
            const int cur = ks & 1;
            if (ks < 3) {
#pragma unroll
                for (int mt = 0; mt < 2; ++mt)
                    ldsm_x4(abuf[cur ^ 1][mt][0], abuf[cur ^ 1][mt][1],
                            abuf[cur ^ 1][mt][2], abuf[cur ^ 1][mt][3],
                            sa + (uint32_t)(mt * 16 * ROWP) * 2 + kOff + 32);
            }
#pragma unroll
            for (int p = 0; p < 4; ++p) {
                const int bc = p & 1;
                if (p < 3) {
                    ldsm_x4(bbuf[bc ^ 1][0], bbuf[bc ^ 1][1],
                            bbuf[bc ^ 1][2], bbuf[bc ^ 1][3],
                            sb + (uint32_t)((p + 1) * 16 * ROWP) * 2 + kOff);
                } else if (ks < 3) {
                    ldsm_x4(bbuf[bc ^ 1][0], bbuf[bc ^ 1][1],
                            bbuf[bc ^ 1][2], bbuf[bc ^ 1][3],
                            sb + kOff + 32);
                }
#pragma unroll
                for (int mt = 0; mt < 2; ++mt) {
                    mma_f16(acc[mt][2 * p],     abuf[cur][mt], bbuf[bc][0],
                            bbuf[bc][2], acc[mt][2 * p]);
                    mma_f16(acc[mt][2 * p + 1], abuf[cur][mt], bbuf[bc][1],
                            bbuf[bc][3], acc[mt][2 * p + 1]);
                }
            }
        }
        __syncwarp();
        if (lane == 0) MBARRIER_ARRIVE(sbase + s * 16 + 8);
    };

    issue(0);
    issue(1);

#pragma unroll
    for (int kt = 0; kt < KTILES; ++kt) {
        compute(kt);
        if (kt + 2 < KTILES) issue(kt + 2);
    }

    // ---------------- register epilogue ----------------
    // acc[mt][n][c]: gate = n>>1, jhalf = n&1;
    //   row = mBase + wm*32 + mt*16 + gid + (c>=2)*8
    //   jj  = jhalf*8 + tig*2 + (c&1);  hidden j = nt*32 + wn*16 + jj
    const int hjBase = nt * 32 + wn * 16;
    float biasI[4], biasF[4], biasO[4], biasG[4];
#pragma unroll
    for (int jh = 0; jh < 2; ++jh)
#pragma unroll
        for (int c1 = 0; c1 < 2; ++c1) {
            const int hj = hjBase + jh * 8 + tig * 2 + c1;
            biasI[jh * 2 + c1] = __ldg(bx + hj)        + __ldg(bh + hj);
            biasF[jh * 2 + c1] = __ldg(bx + 512 + hj)  + __ldg(bh + 512 + hj);
            biasO[jh * 2 + c1] = __ldg(bx + 1024 + hj) + __ldg(bh + 1024 + hj);
            biasG[jh * 2 + c1] = __ldg(bx + 1536 + hj) + __ldg(bh + 1536 + hj);
        }

    float* outH = out + (size_t)BATCH * DH;
#pragma unroll
    for (int mt = 0; mt < 2; ++mt)
#pragma unroll
        for (int rh = 0; rh < 2; ++rh)
#pragma unroll
            for (int jh = 0; jh < 2; ++jh) {
                const int row = mBase + wm * 32 + mt * 16 + gid + rh * 8;
                const int jj0 = jh * 8 + tig * 2;
                const size_t goff = (size_t)row * DH + hjBase + jj0;
                const float2 cin = *(const float2*)(Cin + goff);
                float2 cnew, hnew;
#pragma unroll
                for (int c1 = 0; c1 < 2; ++c1) {
                    const int c = rh * 2 + c1;
                    const int bidx = jh * 2 + c1;
                    const float zi = acc[mt][jh][c]     + biasI[bidx];
                    const float zf = acc[mt][2 + jh][c] + biasF[bidx];
                    const float zo = acc[mt][4 + jh][c] + biasO[bidx];
                    const float zg = acc[mt][6 + jh][c] + biasG[bidx];
                    const float ig = sigm(zi);
                    const float fg = sigm(zf);
                    const float og = sigm(zo);
                    const float gg = tanh_fast(zg);
                    const float cv = fg * ((c1 == 0) ? cin.x : cin.y) + ig * gg;
                    const float hv = og * tanh_fast(cv);
                    if (c1 == 0) { cnew.x = cv; hnew.x = hv; }
                    else         { cnew.y = cv; hnew.y = hv; }
                }
                *(float2*)(out + goff) = cnew;
                *(float2*)(outH + goff) = hnew;
            }
}

extern "C" void kernel_launch(void* const* d_in, const int* in_sizes, int n_in,
                              void* d_out, int out_size) {
    const float* x = (const float*)d_in[0];
    const float* C = (const float*)d_in[1];
    const float* h = (const float*)d_in[2];
    const float* Wx = (const float*)d_in[3];
    const float* bx = (const float*)d_in[4];
    const float* Wh = (const float*)d_in[5];
    const float* bh = (const float*)d_in[6];
    float* out = (float*)d_out;

    cudaFuncSetAttribute(lstm_gemm, cudaFuncAttributeMaxDynamicSharedMemorySize,
                         SMEM_BYTES);

    prep_all<<<PREP_A_BLOCKS + PREP_B_BLOCKS, 256>>>(x, h, Wx, Wh);
    dim3 grid(NTOT / BN, BATCH / BM);  // (16, 256)
    lstm_gemm<<<grid, THREADS, SMEM_BYTES>>>(C, bx, bh, out);
}